// round 2
// baseline (speedup 1.0000x reference)
#include <cuda_runtime.h>
#include <cuda_bf16.h>

// Problem constants
#define B_ROWS 16384
#define DIM    768
#define ATTRS  51
#define NPAD   64
#define BN_EPS 1e-5f

// GEMM tiling
#define BM 128
#define BN 64
#define BK 16
#define XS_STRIDE 132   // padded to dodge bank conflicts on transposed stores
#define NKT (DIM / BK)  // 48
#define GRID_M (B_ROWS / BM)  // 128

// -------- device scratch (no allocations allowed) --------
__device__ float g_wc[DIM * NPAD];            // Wc^T, [k][n] padded, 196 KB
__device__ float g_z[B_ROWS * NPAD];          // padded logits (bias-free), 4 MB
__device__ float g_psum[GRID_M * NPAD];       // per-block partial sums
__device__ float g_psq[GRID_M * NPAD];        // per-block partial sums of squares
__device__ float g_mean[NPAD];
__device__ float g_rstd[NPAD];

// ============================================================
// Kernel A: Wc^T[k][a] = sum_j W_attr[a][j] * W_embed[j][k]
// grid (6 k-chunks of 128, 16 a-groups of 4), 128 threads
// ============================================================
__global__ __launch_bounds__(128) void wc_kernel(const float* __restrict__ W_embed,
                                                 const float* __restrict__ W_attr) {
    __shared__ float s_wa[4 * DIM];
    const int k  = blockIdx.x * 128 + threadIdx.x;     // 0..767
    const int a0 = blockIdx.y * 4;                     // 0..60

    // stage 4 W_attr rows (zero-padded beyond ATTRS)
    for (int i = threadIdx.x; i < 4 * DIM; i += 128) {
        int aa = i / DIM, j = i - aa * DIM;
        int a  = a0 + aa;
        s_wa[i] = (a < ATTRS) ? W_attr[a * DIM + j] : 0.0f;
    }
    __syncthreads();

    float acc0 = 0.f, acc1 = 0.f, acc2 = 0.f, acc3 = 0.f;
#pragma unroll 4
    for (int j = 0; j < DIM; j++) {
        float we = W_embed[j * DIM + k];               // coalesced
        acc0 = fmaf(s_wa[j          ], we, acc0);
        acc1 = fmaf(s_wa[DIM    + j ], we, acc1);
        acc2 = fmaf(s_wa[2*DIM  + j ], we, acc2);
        acc3 = fmaf(s_wa[3*DIM  + j ], we, acc3);
    }
    float* dst = g_wc + k * NPAD + a0;
    dst[0] = acc0; dst[1] = acc1; dst[2] = acc2; dst[3] = acc3;
}

// ============================================================
// Kernel B: z = x @ Wc^T  (M=16384, N=64pad, K=768) fp32 SGEMM
// + per-block BN partials.  grid 128, 256 threads.
// ============================================================
__global__ __launch_bounds__(256) void gemm_kernel(const float* __restrict__ x) {
    __shared__ __align__(16) float xs[BK * XS_STRIDE];   // 8.25 KB
    __shared__ __align__(16) float ws[BK * BN];          // 4 KB
    __shared__ float ssum[BN];
    __shared__ float ssq[BN];

    const int tid  = threadIdx.x;
    const int row0 = blockIdx.x * BM;

    if (tid < BN) { ssum[tid] = 0.0f; ssq[tid] = 0.0f; }

    // global-load mapping for x tile: 2 float4 per thread
    const int lm  = tid >> 2;          // 0..63
    const int lk4 = (tid & 3) * 4;     // 0,4,8,12
    // global-load mapping for w tile: 1 float4 per thread
    const int wk  = tid >> 4;          // 0..15
    const int wn4 = (tid & 15) * 4;    // 0..60
    // compute mapping: 8 rows x 4 cols per thread
    const int tn0 = (tid & 15) * 4;
    const int tm0 = (tid >> 4) * 8;

    const float* xg = x + (size_t)row0 * DIM;

    float acc[8][4];
#pragma unroll
    for (int i = 0; i < 8; i++)
#pragma unroll
        for (int j = 0; j < 4; j++) acc[i][j] = 0.0f;

    // prologue: load tile 0 into registers
    float4 xa0 = *(const float4*)(xg + (size_t)lm * DIM + lk4);
    float4 xa1 = *(const float4*)(xg + (size_t)(lm + 64) * DIM + lk4);
    float4 wa  = *(const float4*)(g_wc + wk * NPAD + wn4);

    // store tile 0 to smem
    xs[(lk4 + 0) * XS_STRIDE + lm] = xa0.x;
    xs[(lk4 + 1) * XS_STRIDE + lm] = xa0.y;
    xs[(lk4 + 2) * XS_STRIDE + lm] = xa0.z;
    xs[(lk4 + 3) * XS_STRIDE + lm] = xa0.w;
    xs[(lk4 + 0) * XS_STRIDE + lm + 64] = xa1.x;
    xs[(lk4 + 1) * XS_STRIDE + lm + 64] = xa1.y;
    xs[(lk4 + 2) * XS_STRIDE + lm + 64] = xa1.z;
    xs[(lk4 + 3) * XS_STRIDE + lm + 64] = xa1.w;
    *(float4*)(ws + wk * BN + wn4) = wa;
    __syncthreads();

    for (int kt = 0; kt < NKT; kt++) {
        // prefetch next tile into registers (overlaps with compute)
        if (kt + 1 < NKT) {
            int k0 = (kt + 1) * BK;
            xa0 = *(const float4*)(xg + (size_t)lm * DIM + k0 + lk4);
            xa1 = *(const float4*)(xg + (size_t)(lm + 64) * DIM + k0 + lk4);
            wa  = *(const float4*)(g_wc + (k0 + wk) * NPAD + wn4);
        }

        // compute current tile
#pragma unroll
        for (int k = 0; k < BK; k++) {
            float4 a0 = *(const float4*)&xs[k * XS_STRIDE + tm0];
            float4 a1 = *(const float4*)&xs[k * XS_STRIDE + tm0 + 4];
            float4 b  = *(const float4*)&ws[k * BN + tn0];
            float am[8] = {a0.x, a0.y, a0.z, a0.w, a1.x, a1.y, a1.z, a1.w};
            float bm[4] = {b.x, b.y, b.z, b.w};
#pragma unroll
            for (int i = 0; i < 8; i++)
#pragma unroll
                for (int j = 0; j < 4; j++)
                    acc[i][j] = fmaf(am[i], bm[j], acc[i][j]);
        }
        __syncthreads();

        if (kt + 1 < NKT) {
            xs[(lk4 + 0) * XS_STRIDE + lm] = xa0.x;
            xs[(lk4 + 1) * XS_STRIDE + lm] = xa0.y;
            xs[(lk4 + 2) * XS_STRIDE + lm] = xa0.z;
            xs[(lk4 + 3) * XS_STRIDE + lm] = xa0.w;
            xs[(lk4 + 0) * XS_STRIDE + lm + 64] = xa1.x;
            xs[(lk4 + 1) * XS_STRIDE + lm + 64] = xa1.y;
            xs[(lk4 + 2) * XS_STRIDE + lm + 64] = xa1.z;
            xs[(lk4 + 3) * XS_STRIDE + lm + 64] = xa1.w;
            *(float4*)(ws + wk * BN + wn4) = wa;
            __syncthreads();
        }
    }

    // epilogue: store z (padded, float4) + BN partials
#pragma unroll
    for (int i = 0; i < 8; i++) {
        float4 v = make_float4(acc[i][0], acc[i][1], acc[i][2], acc[i][3]);
        *(float4*)(g_z + (size_t)(row0 + tm0 + i) * NPAD + tn0) = v;
    }
#pragma unroll
    for (int j = 0; j < 4; j++) {
        float s = 0.f, q = 0.f;
#pragma unroll
        for (int i = 0; i < 8; i++) {
            float v = acc[i][j];
            s += v;
            q = fmaf(v, v, q);
        }
        atomicAdd(&ssum[tn0 + j], s);
        atomicAdd(&ssq[tn0 + j], q);
    }
    __syncthreads();
    if (tid < BN) {
        g_psum[blockIdx.x * NPAD + tid] = ssum[tid];
        g_psq[blockIdx.x * NPAD + tid]  = ssq[tid];
    }
}

// ============================================================
// Kernel C1: reduce partials -> mean, rstd (1 block, 64 threads)
// ============================================================
__global__ void stats_kernel() {
    int n = threadIdx.x;   // 0..63
    float s = 0.f, q = 0.f;
    for (int b = 0; b < GRID_M; b++) {
        s += g_psum[b * NPAD + n];
        q += g_psq[b * NPAD + n];
    }
    const float inv = 1.0f / (float)B_ROWS;
    float mean = s * inv;
    float var  = q * inv - mean * mean;
    g_mean[n] = mean;
    g_rstd[n] = rsqrtf(var + BN_EPS);
}

// ============================================================
// Kernel C2: y = (z - mean) * rstd * gamma + beta -> d_out [B,51]
// ============================================================
__global__ __launch_bounds__(256) void norm_kernel(const float* __restrict__ gamma,
                                                   const float* __restrict__ beta,
                                                   float* __restrict__ out) {
    int idx = blockIdx.x * 256 + threadIdx.x;
    if (idx >= B_ROWS * ATTRS) return;
    int row = idx / ATTRS;
    int n   = idx - row * ATTRS;
    float z = g_z[(size_t)row * NPAD + n];
    out[idx] = (z - g_mean[n]) * g_rstd[n] * gamma[n] + beta[n];
}

// ============================================================
extern "C" void kernel_launch(void* const* d_in, const int* in_sizes, int n_in,
                              void* d_out, int out_size) {
    const float* x       = (const float*)d_in[0];
    const float* W_embed = (const float*)d_in[1];
    // d_in[2] = b_embed  (cancelled exactly by BatchNorm mean-subtraction)
    const float* W_attr  = (const float*)d_in[3];
    // d_in[4] = b_attr   (cancelled exactly by BatchNorm mean-subtraction)
    const float* gamma   = (const float*)d_in[5];
    const float* beta    = (const float*)d_in[6];
    float* out = (float*)d_out;

    wc_kernel<<<dim3(6, 16), 128>>>(W_embed, W_attr);
    gemm_kernel<<<GRID_M, 256>>>(x);
    stats_kernel<<<1, 64>>>();
    norm_kernel<<<(B_ROWS * ATTRS + 255) / 256, 256>>>(gamma, beta, out);
}